// round 9
// baseline (speedup 1.0000x reference)
#include <cuda_runtime.h>

#define DIN    9
#define NPAIR  45
#define NTRI   165

// smem basis layout (floats), channel-natural:
//  A:   9 rows * 4  =  36  @ 0     (ch: [e0, e1p0, e1p1, e1p2])
//  B:  45 rows * 12 = 540  @ 36    (ch: [e2s0..2, e3s0p0..s1p2, pad3])
//  C: 165 rows * 12 = 1980 @ 576   (ch: [e4s0..3, e5s0p0..s1p2, pad2])
#define SB_TOTAL 2556

typedef unsigned long long u64;

__device__ __forceinline__ u64 pk2(float lo, float hi) {
    u64 r; asm("mov.b64 %0, {%1, %2};" : "=l"(r) : "f"(lo), "f"(hi)); return r;
}
__device__ __forceinline__ void upk2(float& lo, float& hi, u64 v) {
    asm("mov.b64 {%0, %1}, %2;" : "=f"(lo), "=f"(hi) : "l"(v));
}
__device__ __forceinline__ u64 ffma2(u64 a, u64 b, u64 c) {
    u64 d; asm("fma.rn.f32x2 %0, %1, %2, %3;" : "=l"(d) : "l"(a), "l"(b), "l"(c)); return d;
}
__device__ __forceinline__ u64 fmul2(u64 a, u64 b) {
    u64 d; asm("mul.rn.f32x2 %0, %1, %2;" : "=l"(d) : "l"(a), "l"(b)); return d;
}

// ---------------------------------------------------------------------------
// 1 item per thread: block = 128 threads = 1 node. Features live as
// duplicated lane-pairs fd[a]=(f_a,f_a) so every packed product (P, F) is
// duplicated for free; channel-pair f32x2 FFMAs, zero dup-MOVs in hot loops.
// Small persistent state (~42 regs) -> high occupancy without spills.
// ---------------------------------------------------------------------------
__global__ void __launch_bounds__(128, 5)
symcon_kernel(const float* __restrict__ feats,   // (N, 1152)
              const int*   __restrict__ species, // (N,)
              const float* __restrict__ b0, const float* __restrict__ b1,
              const float* __restrict__ b2, const float* __restrict__ b3,
              const float* __restrict__ b4, const float* __restrict__ b5,
              const float* __restrict__ W0, const float* __restrict__ W1,
              const float* __restrict__ W2, const float* __restrict__ W3,
              const float* __restrict__ W4, const float* __restrict__ W5,
              float* __restrict__ out)            // (N, 512)
{
    __shared__ float sb[SB_TOTAL];   // 10224 B

    const int m = threadIdx.x;       // 0..127 (item within node)
    const int n = blockIdx.x;        // node

    // ---- hoisted global loads (latency hides behind prep) ----
    const int e = species[n];
    const float* fbase = feats + n * 1152;

    u64 fd[9];
    {
        float v = fbase[m];
        fd[0] = pk2(v, v);
        #pragma unroll
        for (int k = 0; k < 3; k++) { v = fbase[128 + m * 3 + k]; fd[1 + k] = pk2(v, v); }
        #pragma unroll
        for (int k = 0; k < 5; k++) { v = fbase[512 + m * 5 + k]; fd[4 + k] = pk2(v, v); }
    }

    // ---- fused prep: symmetrize bases into smem (128 threads) ----
    if (m < DIN) {
        float* row = sb + m * 4;
        row[0] = b0[m];
        #pragma unroll
        for (int p = 0; p < 3; p++) row[1 + p] = b1[m * 3 + p];
    }
    if (m < NPAIR) {
        int a = 0, rem = m;
        while (rem >= DIN - a) { rem -= DIN - a; a++; }
        const int b = a + rem;
        float* row = sb + 36 + m * 12;
        #pragma unroll
        for (int s = 0; s < 3; s++) {
            float v = b2[(a * 9 + b) * 3 + s];
            if (a != b) v += b2[(b * 9 + a) * 3 + s];
            row[s] = v;
        }
        #pragma unroll
        for (int s = 0; s < 2; s++)
            #pragma unroll
            for (int p = 0; p < 3; p++) {
                float v = b3[((a * 9 + b) * 2 + s) * 3 + p];
                if (a != b) v += b3[((b * 9 + a) * 2 + s) * 3 + p];
                row[3 + s * 3 + p] = v;
            }
        row[9] = 0.f; row[10] = 0.f; row[11] = 0.f;
    }
    for (int t = m; t < NTRI; t += 128) {
        // decode triple index -> (a, b, c), a <= b <= c
        int a = 0, rem = t;
        for (;; a++) {
            const int cnt = (DIN - a) * (DIN - a + 1) / 2;
            if (rem < cnt) break;
            rem -= cnt;
        }
        int b = a;
        for (;; b++) {
            const int cnt = DIN - b;
            if (rem < cnt) break;
            rem -= cnt;
        }
        const int c = b + rem;

        const int pi[6] = {a, a, b, b, c, c};
        const int pj[6] = {b, c, a, c, a, b};
        const int pk[6] = {c, b, c, a, b, a};
        float acc[10];
        #pragma unroll
        for (int q = 0; q < 10; q++) acc[q] = 0.f;
        for (int q = 0; q < 6; q++) {
            bool dup = false;
            for (int r = 0; r < q; r++)
                if (pi[r] == pi[q] && pj[r] == pj[q] && pk[r] == pk[q]) { dup = true; break; }
            if (dup) continue;
            const int base = (pi[q] * 9 + pj[q]) * 9 + pk[q];
            for (int s = 0; s < 4; s++) acc[s] += b4[base * 4 + s];
            for (int s = 0; s < 2; s++)
                for (int p = 0; p < 3; p++)
                    acc[4 + s * 3 + p] += b5[(base * 2 + s) * 3 + p];
        }
        float* row = sb + 576 + t * 12;
        #pragma unroll
        for (int q = 0; q < 10; q++) row[q] = acc[q];
        row[10] = 0.f; row[11] = 0.f;
    }
    __syncthreads();

    // smem views (u64 units; A row a at a*2, B row pr at 18+pr*6, C row t3 at 288+t3*6)
    const u64* sbu = reinterpret_cast<const u64*>(sb);

    // channel-pair accumulators (single item)
    u64 A[2] = {0ull, 0ull};
    u64 B[5] = {0ull, 0ull, 0ull, 0ull, 0ull};
    u64 C[5] = {0ull, 0ull, 0ull, 0ull, 0ull};

    // nu=1
    #pragma unroll
    for (int a = 0; a < 9; a++) {
        const ulonglong2 v = *reinterpret_cast<const ulonglong2*>(sbu + a * 2);
        A[0] = ffma2(v.x, fd[a], A[0]);
        A[1] = ffma2(v.y, fd[a], A[1]);
    }

    // nu=2 + nu=3 fused (multipliers arrive duplicated — no MOVs)
    {
        int pr = 0, t3 = 0;
        #pragma unroll
        for (int a = 0; a < 9; a++) {
            #pragma unroll
            for (int b = a; b < 9; b++) {
                const u64 P = fmul2(fd[a], fd[b]);
                {
                    const u64* r = sbu + 18 + pr * 6;
                    const ulonglong2 v01 = *reinterpret_cast<const ulonglong2*>(r);
                    const ulonglong2 v23 = *reinterpret_cast<const ulonglong2*>(r + 2);
                    const u64 v4 = r[4];
                    B[0] = ffma2(v01.x, P, B[0]);
                    B[1] = ffma2(v01.y, P, B[1]);
                    B[2] = ffma2(v23.x, P, B[2]);
                    B[3] = ffma2(v23.y, P, B[3]);
                    B[4] = ffma2(v4,    P, B[4]);
                }
                #pragma unroll
                for (int c = b; c < 9; c++) {
                    const u64 F = fmul2(P, fd[c]);
                    const u64* r = sbu + 288 + t3 * 6;
                    const ulonglong2 w01 = *reinterpret_cast<const ulonglong2*>(r);
                    const ulonglong2 w23 = *reinterpret_cast<const ulonglong2*>(r + 2);
                    const u64 w4 = r[4];
                    C[0] = ffma2(w01.x, F, C[0]);
                    C[1] = ffma2(w01.y, F, C[1]);
                    C[2] = ffma2(w23.x, F, C[2]);
                    C[3] = ffma2(w23.y, F, C[3]);
                    C[4] = ffma2(w4,    F, C[4]);
                    t3++;
                }
                pr++;
            }
        }
    }

    // ---- epilogue: per-species weight contraction + store ----
    float TA[4], TB[10], TC[10];
    upk2(TA[0], TA[1], A[0]); upk2(TA[2], TA[3], A[1]);
    #pragma unroll
    for (int q = 0; q < 5; q++) upk2(TB[2 * q], TB[2 * q + 1], B[q]);
    #pragma unroll
    for (int q = 0; q < 5; q++) upk2(TC[2 * q], TC[2 * q + 1], C[q]);

    float* obase = out + n * 512;
    {
        float o0 = W0[e * 128 + m] * TA[0];
        #pragma unroll
        for (int s = 0; s < 3; s++) o0 = fmaf(W2[(e * 3 + s) * 128 + m], TB[s], o0);
        #pragma unroll
        for (int s = 0; s < 4; s++) o0 = fmaf(W4[(e * 4 + s) * 128 + m], TC[s], o0);
        obase[m] = o0;
    }
    {
        float o1[3];
        const float w1 = W1[e * 128 + m];
        #pragma unroll
        for (int p = 0; p < 3; p++) o1[p] = w1 * TA[1 + p];
        #pragma unroll
        for (int s = 0; s < 2; s++) {
            const float w = W3[(e * 2 + s) * 128 + m];
            #pragma unroll
            for (int p = 0; p < 3; p++) o1[p] = fmaf(w, TB[3 + s * 3 + p], o1[p]);
        }
        #pragma unroll
        for (int s = 0; s < 2; s++) {
            const float w = W5[(e * 2 + s) * 128 + m];
            #pragma unroll
            for (int p = 0; p < 3; p++) o1[p] = fmaf(w, TC[4 + s * 3 + p], o1[p]);
        }
        #pragma unroll
        for (int p = 0; p < 3; p++) obase[128 + m * 3 + p] = o1[p];
    }
}

// ---------------------------------------------------------------------------
extern "C" void kernel_launch(void* const* d_in, const int* in_sizes, int n_in,
                              void* d_out, int out_size)
{
    const float* feats   = (const float*)d_in[0];
    const int*   species = (const int*)  d_in[1];
    const float* b0 = (const float*)d_in[2];
    const float* w0 = (const float*)d_in[3];
    const float* b1 = (const float*)d_in[4];
    const float* w1 = (const float*)d_in[5];
    const float* b2 = (const float*)d_in[6];
    const float* w2 = (const float*)d_in[7];
    const float* b3 = (const float*)d_in[8];
    const float* w3 = (const float*)d_in[9];
    const float* b4 = (const float*)d_in[10];
    const float* w4 = (const float*)d_in[11];
    const float* b5 = (const float*)d_in[12];
    const float* w5 = (const float*)d_in[13];
    float* out = (float*)d_out;

    symcon_kernel<<<2048, 128>>>(feats, species,
                                 b0, b1, b2, b3, b4, b5,
                                 w0, w1, w2, w3, w4, w5, out);
}